// round 2
// baseline (speedup 1.0000x reference)
#include <cuda_runtime.h>
#include <cstdint>
#include <cmath>

#define BATCH 16384
#define NV 1024
#define NH 1024
#define HD 64
#define KSTEPS 10

// ---------------- scratch (device globals; no allocation allowed) ----------------
__device__ float  g_bmod[(size_t)BATCH * NV];   // 64 MB
__device__ float  g_cmod[(size_t)BATCH * NH];   // 64 MB
__device__ float  g_v   [(size_t)BATCH * NV];   // 64 MB  chain state v
__device__ float  g_h   [(size_t)BATCH * NH];   // 64 MB  h samples / vW scratch
__device__ float  g_a   [(size_t)BATCH * NV];   // 64 MB  a = h @ W^T
__device__ float  g_u   [BATCH];
__device__ float  g_Wt  [(size_t)NV * NH];      // 4 MB   W transposed
__device__ float  g_colsum[NH];
__device__ double g_acc;

// ---------------- threefry2x32 (JAX, 20 rounds) ----------------
__host__ __device__ __forceinline__ void tf2x32(uint32_t k0, uint32_t k1,
                                                uint32_t x0, uint32_t x1,
                                                uint32_t& o0, uint32_t& o1) {
  uint32_t ks2 = k0 ^ k1 ^ 0x1BD11BDAu;
#define TF_R(r) { x0 += x1; x1 = (x1 << (r)) | (x1 >> (32 - (r))); x1 ^= x0; }
  x0 += k0; x1 += k1;
  TF_R(13) TF_R(15) TF_R(26) TF_R(6)   x0 += k1;  x1 += ks2 + 1u;
  TF_R(17) TF_R(29) TF_R(16) TF_R(24)  x0 += ks2; x1 += k0 + 2u;
  TF_R(13) TF_R(15) TF_R(26) TF_R(6)   x0 += k0;  x1 += k1 + 3u;
  TF_R(17) TF_R(29) TF_R(16) TF_R(24)  x0 += k1;  x1 += ks2 + 4u;
  TF_R(13) TF_R(15) TF_R(26) TF_R(6)   x0 += ks2; x1 += k0 + 5u;
#undef TF_R
  o0 = x0; o1 = x1;
}

// jax_threefry_partitionable=True (default in modern JAX):
// random_bits at flat index i = out0 ^ out1 of threefry(key, (hi=0, lo=i))
__device__ __forceinline__ float jax_uniform(uint32_t ka, uint32_t kb, uint32_t idx) {
  uint32_t o0, o1; tf2x32(ka, kb, 0u, idx, o0, o1);
  uint32_t bits = o0 ^ o1;
  return __uint_as_float((bits >> 9) | 0x3f800000u) - 1.0f;
}

__device__ __forceinline__ float sigmoidf_(float x)  { return 1.0f / (1.0f + expf(-x)); }
__device__ __forceinline__ float softplusf_(float x) { return fmaxf(x, 0.0f) + log1pf(expf(-fabsf(x))); }

// ---------------- hypernetwork biases ----------------
#define BT_ROWS 16
__global__ void biases_kernel(const float* __restrict__ cond,
                              const float* __restrict__ b,
                              const float* __restrict__ c,
                              const float* __restrict__ fc1w,
                              const float* __restrict__ fc1b,
                              const float* __restrict__ fc2w,
                              const float* __restrict__ fc2b) {
  __shared__ float xs[BT_ROWS][HD];
  int r0 = blockIdx.x * BT_ROWS;
  int tid = threadIdx.x;
  for (int t = tid; t < BT_ROWS * HD; t += blockDim.x) {
    int r = t / HD, d = t % HD;
    xs[r][d] = tanhf(cond[r0 + r] * fc1w[d] + fc1b[d]);
  }
  __syncthreads();
  for (int j = tid; j < NV + NH; j += blockDim.x) {
    int gw, bw;
    if (j < NV) { gw = j;            bw = NV + j; }
    else        { gw = 2*NV + (j-NV); bw = 2*NV + NH + (j-NV); }
    const float* wg = fc2w + (size_t)gw * HD;
    const float* wb = fc2w + (size_t)bw * HD;
    float accG[BT_ROWS], accB[BT_ROWS];
#pragma unroll
    for (int r = 0; r < BT_ROWS; r++) { accG[r] = 0.f; accB[r] = 0.f; }
    for (int d = 0; d < HD; d++) {
      float g = wg[d], bb = wb[d];
#pragma unroll
      for (int r = 0; r < BT_ROWS; r++) {
        float x = xs[r][d];
        accG[r] += g * x;
        accB[r] += bb * x;
      }
    }
    float gbias = fc2b[gw], bbias = fc2b[bw];
    if (j < NV) {
      float bj = b[j];
      for (int r = 0; r < BT_ROWS; r++)
        g_bmod[(size_t)(r0 + r) * NV + j] = (1.0f + accG[r] + gbias) * bj + (accB[r] + bbias);
    } else {
      int hh = j - NV; float ch = c[hh];
      for (int r = 0; r < BT_ROWS; r++)
        g_cmod[(size_t)(r0 + r) * NH + hh] = (1.0f + accG[r] + gbias) * ch + (accB[r] + bbias);
    }
  }
}

// ---------------- setup ----------------
__global__ void transpose_kernel(const float* __restrict__ W) {
  __shared__ float t[32][33];
  int bx = blockIdx.x * 32, by = blockIdx.y * 32;
  for (int i = 0; i < 32; i += 8)
    t[threadIdx.y + i][threadIdx.x] = W[(size_t)(by + threadIdx.y + i) * NH + bx + threadIdx.x];
  __syncthreads();
  for (int i = 0; i < 32; i += 8)
    g_Wt[(size_t)(bx + threadIdx.y + i) * NV + by + threadIdx.x] = t[threadIdx.x][threadIdx.y + i];
}

__global__ void colsum_kernel(const float* __restrict__ W) {
  int h = blockIdx.x * blockDim.x + threadIdx.x;
  float s = 0.f;
  for (int v2 = 0; v2 < NV; v2++) s += W[(size_t)v2 * NH + h];
  g_colsum[h] = s;
}

__global__ void copyv_kernel(const float* __restrict__ v_data) {
  int i = blockIdx.x * blockDim.x + threadIdx.x;
  g_v[i] = v_data[i];
}

__global__ void u0_kernel(uint32_t ka, uint32_t kb) {
  int i = blockIdx.x * blockDim.x + threadIdx.x;
  if (i == 0) g_acc = 0.0;
  if (i < BATCH) {
    float un = jax_uniform(ka, kb, (uint32_t)i);
    g_u[i] = (un < 0.5f) ? 1.0f : 0.0f;
  }
}

// ---------------- tiled SGEMM with fused operand/epilogue ----------------
// MODE 1: A = v_branch(g_v, g_u), B = W,    C = g_h  (epilogue: sigmoid(+c_mod) + bernoulli(kh))
// MODE 2: A = g_h,                B = g_Wt, C = g_a
// MODE 3: A = Aparam (v_data),    B = W,    C = g_h  (raw vW)
// MODE 4: A = g_v,                B = W,    C = g_h  (raw vW)
#define BM 128
#define BN 64
#define BK 16
template<int MODE>
__global__ void gemm_kernel(const float* __restrict__ Aparam,
                            const float* __restrict__ Wparam,
                            uint32_t ka, uint32_t kb) {
  const float* A   = (MODE == 3) ? Aparam : (MODE == 2 ? (const float*)g_h : (const float*)g_v);
  const float* Bm  = (MODE == 2) ? (const float*)g_Wt : Wparam;
  float*       C   = (MODE == 2) ? g_a : g_h;

  __shared__ float As[BK][BM];
  __shared__ float Bs[BK][BN];
  int tid = threadIdx.x;            // 256 threads
  int tx = tid & 15;                // N direction
  int ty = tid >> 4;                // M direction
  int bm = blockIdx.y * BM;
  int bn = blockIdx.x * BN;

  int aRow0 = tid >> 2;             // 0..63, also +64
  int aCol4 = (tid & 3) * 4;
  int bRow  = tid >> 4;             // 0..15
  int bCol4 = (tid & 15) * 4;

  float uflip0 = 1.0f, uflip1 = 1.0f;
  if (MODE == 1) {
    uflip0 = g_u[bm + aRow0];
    uflip1 = g_u[bm + aRow0 + 64];
  }

  float acc[8][4];
#pragma unroll
  for (int i = 0; i < 8; i++)
#pragma unroll
    for (int j = 0; j < 4; j++) acc[i][j] = 0.f;

  for (int k0 = 0; k0 < 1024; k0 += BK) {
#pragma unroll
    for (int half = 0; half < 2; half++) {
      int r  = aRow0 + half * 64;
      int gr = bm + r;
      float4 av = *(const float4*)(A + (size_t)gr * 1024 + k0 + aCol4);
      if (MODE == 1) {
        float uu = half ? uflip1 : uflip0;
        if (uu == 0.0f) { av.x = 1.f-av.x; av.y = 1.f-av.y; av.z = 1.f-av.z; av.w = 1.f-av.w; }
      }
      As[aCol4 + 0][r] = av.x; As[aCol4 + 1][r] = av.y;
      As[aCol4 + 2][r] = av.z; As[aCol4 + 3][r] = av.w;
    }
    {
      float4 bv = *(const float4*)(Bm + (size_t)(k0 + bRow) * 1024 + bn + bCol4);
      *(float4*)&Bs[bRow][bCol4] = bv;
    }
    __syncthreads();
#pragma unroll
    for (int kk = 0; kk < BK; kk++) {
      float ar[8], br[4];
#pragma unroll
      for (int i = 0; i < 8; i++) ar[i] = As[kk][ty * 8 + i];
#pragma unroll
      for (int j = 0; j < 4; j++) br[j] = Bs[kk][tx * 4 + j];
#pragma unroll
      for (int i = 0; i < 8; i++)
#pragma unroll
        for (int j = 0; j < 4; j++) acc[i][j] += ar[i] * br[j];
    }
    __syncthreads();
  }

#pragma unroll
  for (int i = 0; i < 8; i++) {
    int r = bm + ty * 8 + i;
#pragma unroll
    for (int j = 0; j < 4; j++) {
      int cc = bn + tx * 4 + j;
      uint32_t idx = (uint32_t)r * 1024u + (uint32_t)cc;
      if (MODE == 1) {
        float p  = sigmoidf_(acc[i][j] + g_cmod[idx]);
        float un = jax_uniform(ka, kb, idx);
        C[idx] = (un < p) ? 1.0f : 0.0f;
      } else {
        C[idx] = acc[i][j];
      }
    }
  }
}

// ---------------- dE reduce + sample u ----------------
__global__ void dE_kernel(uint32_t ka, uint32_t kb) {
  int row = blockIdx.x;
  int tid = threadIdx.x;
  const float* a  = g_a    + (size_t)row * NV;
  const float* bm = g_bmod + (size_t)row * NV;
  const float* v  = g_v    + (size_t)row * NV;
  float sa = 0, sb = 0, sva = 0, svb = 0;
  for (int j = tid; j < NV; j += 256) {
    float aj = a[j], bj = bm[j], vj = v[j];
    sa += aj; sb += bj; sva += vj * aj; svb += vj * bj;
  }
  __shared__ float red[4][256];
  red[0][tid] = sa; red[1][tid] = sb; red[2][tid] = sva; red[3][tid] = svb;
  __syncthreads();
  for (int s = 128; s > 0; s >>= 1) {
    if (tid < s)
      for (int q = 0; q < 4; q++) red[q][tid] += red[q][tid + s];
    __syncthreads();
  }
  if (tid == 0) {
    float dE = -red[1][0] - red[0][0] + 2.0f * red[3][0] + 2.0f * red[2][0];
    float p  = sigmoidf_(dE);
    float un = jax_uniform(ka, kb, (uint32_t)row);
    g_u[row] = (un < p) ? 1.0f : 0.0f;
  }
}

// ---------------- sample v_next ----------------
__global__ void sampleV_kernel(uint32_t ka, uint32_t kb) {
  uint32_t idx = blockIdx.x * blockDim.x + threadIdx.x;
  float p   = sigmoidf_(g_a[idx] + g_bmod[idx]);
  float un  = jax_uniform(ka, kb, idx);
  float vbn = (un < p) ? 1.0f : 0.0f;
  float uu  = g_u[idx >> 10];
  g_v[idx]  = (uu != 0.0f) ? vbn : 1.0f - vbn;
}

// ---------------- free energy (vW already in g_h) ----------------
template<bool USE_GV>
__global__ void fe_kernel(const float* __restrict__ vparam, double sign) {
  int row = blockIdx.x;
  int tid = threadIdx.x;
  const float* vr = (USE_GV ? (const float*)g_v : vparam) + (size_t)row * NV;
  const float* br = g_bmod + (size_t)row * NV;
  const float* wr = g_h    + (size_t)row * NH;
  const float* cr = g_cmod + (size_t)row * NH;
  float spn = 0, spf = 0, svb = 0, sb = 0;
  for (int j = tid; j < NV; j += 256) {
    float vv = vr[j], bb = br[j];
    svb += vv * bb; sb += bb;
    float w = wr[j], cm = cr[j];
    spn += softplusf_(w + cm);
    spf += softplusf_(g_colsum[j] - w + cm);
  }
  __shared__ float red[4][256];
  red[0][tid] = spn; red[1][tid] = spf; red[2][tid] = svb; red[3][tid] = sb;
  __syncthreads();
  for (int s = 128; s > 0; s >>= 1) {
    if (tid < s)
      for (int q = 0; q < 4; q++) red[q][tid] += red[q][tid + s];
    __syncthreads();
  }
  if (tid == 0) {
    float Fn = -red[2][0] - red[0][0];
    float Ff = -(red[3][0] - red[2][0]) - red[1][0];
    float a1 = -Fn, a2 = -Ff;
    float m  = fmaxf(a1, a2);
    float lse = m + logf(expf(a1 - m) + expf(a2 - m));
    atomicAdd(&g_acc, sign * (double)(-lse));
  }
}

__global__ void final_kernel(float* out) {
  out[0] = (float)(g_acc / (double)BATCH);
}

// ---------------- host ----------------
struct K2 { uint32_t a, b; };
static inline K2 tf_child(K2 k, uint32_t i) {
  K2 r; tf2x32(k.a, k.b, 0u, i, r.a, r.b);  // partitionable fold-like split
  return r;
}

extern "C" void kernel_launch(void* const* d_in, const int* in_sizes, int n_in,
                              void* d_out, int out_size) {
  (void)in_sizes; (void)n_in; (void)out_size;
  const float* v_data = (const float*)d_in[0];
  const float* cond   = (const float*)d_in[1];
  const float* W      = (const float*)d_in[2];
  const float* b      = (const float*)d_in[3];
  const float* c      = (const float*)d_in[4];
  const float* fc1w   = (const float*)d_in[5];
  const float* fc1b   = (const float*)d_in[6];
  const float* fc2w   = (const float*)d_in[7];
  const float* fc2b   = (const float*)d_in[8];

  // key derivation: key(42) -> (0,42); split -> k_u, k_chain; split(k_chain,10); split(sk,3)
  K2 root = {0u, 42u};
  K2 k_u    = tf_child(root, 0u);
  K2 k_chain= tf_child(root, 1u);
  K2 kh[KSTEPS], ku[KSTEPS], kv[KSTEPS];
  for (int s = 0; s < KSTEPS; s++) {
    K2 sk = tf_child(k_chain, (uint32_t)s);
    kh[s] = tf_child(sk, 0u);
    ku[s] = tf_child(sk, 1u);
    kv[s] = tf_child(sk, 2u);
  }

  dim3 gemmGrid(NH / BN, BATCH / BM);   // (16, 128)

  biases_kernel<<<BATCH / BT_ROWS, 256>>>(cond, b, c, fc1w, fc1b, fc2w, fc2b);
  transpose_kernel<<<dim3(NH / 32, NV / 32), dim3(32, 8)>>>(W);
  colsum_kernel<<<NH / 256, 256>>>(W);
  copyv_kernel<<<(BATCH * NV) / 256, 256>>>(v_data);
  u0_kernel<<<BATCH / 256, 256>>>(k_u.a, k_u.b);

  for (int s = 0; s < KSTEPS; s++) {
    gemm_kernel<1><<<gemmGrid, 256>>>(nullptr, W, kh[s].a, kh[s].b);   // vW + sample h
    gemm_kernel<2><<<gemmGrid, 256>>>(nullptr, W, 0u, 0u);             // a = h @ W^T
    dE_kernel<<<BATCH, 256>>>(ku[s].a, ku[s].b);                       // sample u
    sampleV_kernel<<<(BATCH * NV) / 256, 256>>>(kv[s].a, kv[s].b);     // sample v_next
  }

  // free energy: data (+) then model (-)
  gemm_kernel<3><<<gemmGrid, 256>>>(v_data, W, 0u, 0u);
  fe_kernel<false><<<BATCH, 256>>>(v_data, +1.0);
  gemm_kernel<4><<<gemmGrid, 256>>>(nullptr, W, 0u, 0u);
  fe_kernel<true><<<BATCH, 256>>>(nullptr, -1.0);

  final_kernel<<<1, 1>>>((float*)d_out);
}